// round 1
// baseline (speedup 1.0000x reference)
#include <cuda_runtime.h>
#include <cstdint>

#define B_ 32
#define S_ 1024
#define D_ 512
#define SCALE 0.044194173824159216f   // 1/sqrt(512)

// Fallback scratch in case out_size does not include the attn_sm output.
__device__ float g_attn_scratch[(size_t)B_ * S_ * S_];

__device__ __forceinline__ float to_tf32(float x) {
    float r;
    asm("cvt.rna.tf32.f32 %0, %1;" : "=f"(r) : "f"(x));
    return r;
}

__device__ __forceinline__ void mma_tf32(float* c, const float* a, const float* b) {
    asm volatile(
        "mma.sync.aligned.m16n8k8.row.col.f32.tf32.tf32.f32 "
        "{%0,%1,%2,%3}, {%4,%5,%6,%7}, {%8,%9}, {%0,%1,%2,%3};\n"
        : "+f"(c[0]), "+f"(c[1]), "+f"(c[2]), "+f"(c[3])
        : "r"(__float_as_uint(a[0])), "r"(__float_as_uint(a[1])),
          "r"(__float_as_uint(a[2])), "r"(__float_as_uint(a[3])),
          "r"(__float_as_uint(b[0])), "r"(__float_as_uint(b[1])));
}

// ---------------------------------------------------------------------------
// Kernel 1: masked_vec[b,m,n] = (Q[b,m,:]·K[b,n,:]) * SCALE * mask(b,m,n)
// mask = rep[b,m] && rep[b,n] && (n < m). Upper-tri blocks: zero-fill only.
// 128x128 tile, BK=32, 8 warps (2x4), warp tile 64x32, m16n8k8 tf32.
// ---------------------------------------------------------------------------
__global__ __launch_bounds__(256) void qk_kernel(
    const float* __restrict__ Q, const float* __restrict__ K,
    const int* __restrict__ rep, float* attn_param)
{
    float* attn = attn_param ? attn_param : g_attn_scratch;
    const int bm = blockIdx.y, bn = blockIdx.x, b = blockIdx.z;
    const int m0 = bm * 128, n0 = bn * 128;
    const int tid = threadIdx.x;
    float* attn_b = attn + (size_t)b * S_ * S_;

    if (bn > bm) {
        // Entire tile strictly above diagonal -> masked to zero.
        float4 z = make_float4(0.f, 0.f, 0.f, 0.f);
        #pragma unroll
        for (int i = 0; i < 16; i++) {
            int idx = tid + i * 256;      // 4096 float4 total
            int r = idx >> 5, c = idx & 31;
            reinterpret_cast<float4*>(attn_b + (size_t)(m0 + r) * S_ + n0)[c] = z;
        }
        return;
    }

    __shared__ float As[128 * 40];
    __shared__ float Bs[128 * 40];

    const int warp = tid >> 5, lane = tid & 31;
    const int wm = warp & 1;        // 0..1 -> 64 rows each
    const int wn = warp >> 1;       // 0..3 -> 32 cols each
    const int gID = lane >> 2, tig = lane & 3;

    float acc[4][4][4];
    #pragma unroll
    for (int i = 0; i < 4; i++)
        #pragma unroll
        for (int j = 0; j < 4; j++)
            #pragma unroll
            for (int r = 0; r < 4; r++) acc[i][j][r] = 0.f;

    const float* Qb = Q + ((size_t)b * S_ + m0) * D_;
    const float* Kb = K + ((size_t)b * S_ + n0) * D_;

    for (int kk = 0; kk < D_; kk += 32) {
        #pragma unroll
        for (int i = 0; i < 4; i++) {
            int idx = tid + i * 256;          // 1024 float4 per tile
            int r = idx >> 3, c4 = idx & 7;
            float4 qa = *reinterpret_cast<const float4*>(Qb + (size_t)r * D_ + kk + c4 * 4);
            qa.x = to_tf32(qa.x); qa.y = to_tf32(qa.y);
            qa.z = to_tf32(qa.z); qa.w = to_tf32(qa.w);
            *reinterpret_cast<float4*>(&As[r * 40 + c4 * 4]) = qa;
            float4 ka = *reinterpret_cast<const float4*>(Kb + (size_t)r * D_ + kk + c4 * 4);
            ka.x = to_tf32(ka.x); ka.y = to_tf32(ka.y);
            ka.z = to_tf32(ka.z); ka.w = to_tf32(ka.w);
            *reinterpret_cast<float4*>(&Bs[r * 40 + c4 * 4]) = ka;
        }
        __syncthreads();

        #pragma unroll
        for (int ks = 0; ks < 4; ks++) {
            const int k0 = ks * 8;
            float a[4][4];
            #pragma unroll
            for (int im = 0; im < 4; im++) {
                int r = wm * 64 + im * 16 + gID;
                a[im][0] = As[r * 40 + k0 + tig];
                a[im][1] = As[(r + 8) * 40 + k0 + tig];
                a[im][2] = As[r * 40 + k0 + 4 + tig];
                a[im][3] = As[(r + 8) * 40 + k0 + 4 + tig];
            }
            float bf[4][2];
            #pragma unroll
            for (int in_ = 0; in_ < 4; in_++) {
                int n = wn * 32 + in_ * 8 + gID;
                bf[in_][0] = Bs[n * 40 + k0 + tig];
                bf[in_][1] = Bs[n * 40 + k0 + 4 + tig];
            }
            #pragma unroll
            for (int im = 0; im < 4; im++)
                #pragma unroll
                for (int in_ = 0; in_ < 4; in_++)
                    mma_tf32(acc[im][in_], a[im], bf[in_]);
        }
        __syncthreads();
    }

    // Epilogue: scale + mask, write masked_vec.
    const int* repb = rep + b * S_;
    #pragma unroll
    for (int im = 0; im < 4; im++) {
        int mA = m0 + wm * 64 + im * 16 + gID;
        int mB = mA + 8;
        int rqA = repb[mA], rqB = repb[mB];
        #pragma unroll
        for (int in_ = 0; in_ < 4; in_++) {
            int n = n0 + wn * 32 + in_ * 8 + tig * 2;
            int rk0 = repb[n], rk1 = repb[n + 1];
            float v00 = acc[im][in_][0] * SCALE;
            float v01 = acc[im][in_][1] * SCALE;
            float v10 = acc[im][in_][2] * SCALE;
            float v11 = acc[im][in_][3] * SCALE;
            attn_b[(size_t)mA * S_ + n]     = (n     < mA && rqA && rk0) ? v00 : 0.f;
            attn_b[(size_t)mA * S_ + n + 1] = (n + 1 < mA && rqA && rk1) ? v01 : 0.f;
            attn_b[(size_t)mB * S_ + n]     = (n     < mB && rqB && rk0) ? v10 : 0.f;
            attn_b[(size_t)mB * S_ + n + 1] = (n + 1 < mB && rqB && rk1) ? v11 : 0.f;
        }
    }
}

// ---------------------------------------------------------------------------
// Kernel 2: in-place row softmax, faithful to reference semantics:
//   max over masked_vec (zeros included), exp(v-max)*mask, sums+= (sums==0),
//   attn = masked_exps/(sums+1e-20).
// One block (256 threads) per row; row fits in registers (4 floats/thread).
// ---------------------------------------------------------------------------
__global__ __launch_bounds__(256) void softmax_kernel(
    float* attn_param, const int* __restrict__ rep)
{
    float* attn = attn_param ? attn_param : g_attn_scratch;
    const int q = blockIdx.x, b = blockIdx.y;
    float* row = attn + ((size_t)b * S_ + q) * S_;
    const int tid = threadIdx.x;

    float4 v = reinterpret_cast<float4*>(row)[tid];
    const int k0 = tid * 4;
    const int rq = rep[b * S_ + q];
    const int4 rk = reinterpret_cast<const int4*>(rep + b * S_)[tid];

    __shared__ float red_max[8];
    __shared__ float red_sum[8];

    // max over stored masked_vec (zeros at masked spots already present)
    float mx = fmaxf(fmaxf(v.x, v.y), fmaxf(v.z, v.w));
    #pragma unroll
    for (int o = 16; o; o >>= 1) mx = fmaxf(mx, __shfl_xor_sync(0xffffffffu, mx, o));
    if ((tid & 31) == 0) red_max[tid >> 5] = mx;
    __syncthreads();
    mx = red_max[0];
    #pragma unroll
    for (int w = 1; w < 8; w++) mx = fmaxf(mx, red_max[w]);

    const bool m0b = (k0     < q) && rq && rk.x;
    const bool m1b = (k0 + 1 < q) && rq && rk.y;
    const bool m2b = (k0 + 2 < q) && rq && rk.z;
    const bool m3b = (k0 + 3 < q) && rq && rk.w;
    float e0 = m0b ? __expf(v.x - mx) : 0.f;
    float e1 = m1b ? __expf(v.y - mx) : 0.f;
    float e2 = m2b ? __expf(v.z - mx) : 0.f;
    float e3 = m3b ? __expf(v.w - mx) : 0.f;

    float s = (e0 + e1) + (e2 + e3);
    #pragma unroll
    for (int o = 16; o; o >>= 1) s += __shfl_xor_sync(0xffffffffu, s, o);
    if ((tid & 31) == 0) red_sum[tid >> 5] = s;
    __syncthreads();
    s = red_sum[0];
    #pragma unroll
    for (int w = 1; w < 8; w++) s += red_sum[w];

    float s2 = s + ((s == 0.f) ? 1.f : 0.f);
    float inv = 1.f / (s2 + 1e-20f);

    v.x = e0 * inv; v.y = e1 * inv; v.z = e2 * inv; v.w = e3 * inv;
    reinterpret_cast<float4*>(row)[tid] = v;
}

// ---------------------------------------------------------------------------
// Kernel 3: out[b,m,d] = sum_k attn_sm[b,m,k] * V[b,k,d].
// attn strictly lower-triangular -> K-loop only up to (bm+1)*128.
// ---------------------------------------------------------------------------
__global__ __launch_bounds__(256) void pv_kernel(
    const float* attn_param, const float* __restrict__ V, float* __restrict__ out)
{
    const float* attn = attn_param ? attn_param : g_attn_scratch;
    const int bm = blockIdx.y, bn = blockIdx.x, b = blockIdx.z;
    const int m0 = bm * 128, n0 = bn * 128;
    const int tid = threadIdx.x;

    __shared__ float As[128 * 40];
    __shared__ float Bs[32 * 132];

    const int warp = tid >> 5, lane = tid & 31;
    const int wm = warp & 1, wn = warp >> 1;
    const int gID = lane >> 2, tig = lane & 3;

    float acc[4][4][4];
    #pragma unroll
    for (int i = 0; i < 4; i++)
        #pragma unroll
        for (int j = 0; j < 4; j++)
            #pragma unroll
            for (int r = 0; r < 4; r++) acc[i][j][r] = 0.f;

    const float* Ab = attn + ((size_t)b * S_ + m0) * S_;
    const float* Vb = V + (size_t)b * S_ * D_;
    const int kmax = (bm + 1) * 128;

    for (int kk = 0; kk < kmax; kk += 32) {
        #pragma unroll
        for (int i = 0; i < 4; i++) {
            int idx = tid + i * 256;
            {   // A: attn tile 128 x 32
                int r = idx >> 3, c4 = idx & 7;
                float4 aa = *reinterpret_cast<const float4*>(Ab + (size_t)r * S_ + kk + c4 * 4);
                aa.x = to_tf32(aa.x); aa.y = to_tf32(aa.y);
                aa.z = to_tf32(aa.z); aa.w = to_tf32(aa.w);
                *reinterpret_cast<float4*>(&As[r * 40 + c4 * 4]) = aa;
            }
            {   // B: V tile 32 x 128
                int r = idx >> 5, c4 = idx & 31;
                float4 vv = *reinterpret_cast<const float4*>(Vb + (size_t)(kk + r) * D_ + n0 + c4 * 4);
                vv.x = to_tf32(vv.x); vv.y = to_tf32(vv.y);
                vv.z = to_tf32(vv.z); vv.w = to_tf32(vv.w);
                *reinterpret_cast<float4*>(&Bs[r * 132 + c4 * 4]) = vv;
            }
        }
        __syncthreads();

        #pragma unroll
        for (int ks = 0; ks < 4; ks++) {
            const int k0 = ks * 8;
            float a[4][4];
            #pragma unroll
            for (int im = 0; im < 4; im++) {
                int r = wm * 64 + im * 16 + gID;
                a[im][0] = As[r * 40 + k0 + tig];
                a[im][1] = As[(r + 8) * 40 + k0 + tig];
                a[im][2] = As[r * 40 + k0 + 4 + tig];
                a[im][3] = As[(r + 8) * 40 + k0 + 4 + tig];
            }
            float bf[4][2];
            #pragma unroll
            for (int in_ = 0; in_ < 4; in_++) {
                int n = wn * 32 + in_ * 8 + gID;
                bf[in_][0] = Bs[(k0 + tig) * 132 + n];
                bf[in_][1] = Bs[(k0 + 4 + tig) * 132 + n];
            }
            #pragma unroll
            for (int im = 0; im < 4; im++)
                #pragma unroll
                for (int in_ = 0; in_ < 4; in_++)
                    mma_tf32(acc[im][in_], a[im], bf[in_]);
        }
        __syncthreads();
    }

    #pragma unroll
    for (int im = 0; im < 4; im++) {
        int mA = m0 + wm * 64 + im * 16 + gID;
        int mB = mA + 8;
        #pragma unroll
        for (int in_ = 0; in_ < 4; in_++) {
            int n = n0 + wn * 32 + in_ * 8 + tig * 2;
            out[((size_t)b * S_ + mA) * D_ + n]     = acc[im][in_][0];
            out[((size_t)b * S_ + mA) * D_ + n + 1] = acc[im][in_][1];
            out[((size_t)b * S_ + mB) * D_ + n]     = acc[im][in_][2];
            out[((size_t)b * S_ + mB) * D_ + n + 1] = acc[im][in_][3];
        }
    }
}

extern "C" void kernel_launch(void* const* d_in, const int* in_sizes, int n_in,
                              void* d_out, int out_size)
{
    const float* q   = (const float*)d_in[0];
    const float* k   = (const float*)d_in[1];
    const float* v   = (const float*)d_in[2];
    const int*   rep = (const int*)d_in[3];
    float* out = (float*)d_out;

    const long OUT_ELEMS  = (long)B_ * S_ * D_;   // 16,777,216
    const long ATTN_ELEMS = (long)B_ * S_ * S_;   // 33,554,432

    // Tuple output (out, attn_sm) flattened: out first, then attn_sm.
    float* attn = nullptr;  // nullptr -> kernels fall back to g_attn_scratch
    if ((long)out_size >= OUT_ELEMS + ATTN_ELEMS)
        attn = out + OUT_ELEMS;

    dim3 g1(8, 8, B_);      // (n_tiles, m_tiles, batch)
    qk_kernel<<<g1, 256>>>(q, k, rep, attn);

    dim3 g2(S_, B_);
    softmax_kernel<<<g2, 256>>>(attn, rep);

    dim3 g3(4, 8, B_);      // D/128 = 4 n-tiles
    pv_kernel<<<g3, 256>>>(attn, v, out);
}

// round 2
// speedup vs baseline: 1.1578x; 1.1578x over previous
#include <cuda_runtime.h>
#include <cstdint>

#define B_ 32
#define S_ 1024
#define D_ 512
#define SCALE 0.044194173824159216f   // 1/sqrt(512)

// Fallback scratch in case out_size does not include the attn_sm output.
__device__ float g_attn_scratch[(size_t)B_ * S_ * S_];

__device__ __forceinline__ float to_tf32(float x) {
    float r;
    asm("cvt.rna.tf32.f32 %0, %1;" : "=f"(r) : "f"(x));
    return r;
}
__device__ __forceinline__ float u_tf32(uint32_t u) {
    float r;
    asm("cvt.rna.tf32.f32 %0, %1;" : "=f"(r) : "f"(__uint_as_float(u)));
    return r;
}

__device__ __forceinline__ void mma_tf32(float* c, const float* a, const float* b) {
    asm volatile(
        "mma.sync.aligned.m16n8k8.row.col.f32.tf32.tf32.f32 "
        "{%0,%1,%2,%3}, {%4,%5,%6,%7}, {%8,%9}, {%0,%1,%2,%3};\n"
        : "+f"(c[0]), "+f"(c[1]), "+f"(c[2]), "+f"(c[3])
        : "r"(__float_as_uint(a[0])), "r"(__float_as_uint(a[1])),
          "r"(__float_as_uint(a[2])), "r"(__float_as_uint(a[3])),
          "r"(__float_as_uint(b[0])), "r"(__float_as_uint(b[1])));
}

__device__ __forceinline__ void ldsm4(uint32_t& r0, uint32_t& r1, uint32_t& r2, uint32_t& r3, uint32_t a) {
    asm volatile("ldmatrix.sync.aligned.m8n8.x4.shared.b16 {%0,%1,%2,%3}, [%4];"
                 : "=r"(r0), "=r"(r1), "=r"(r2), "=r"(r3) : "r"(a));
}
__device__ __forceinline__ void ldsm2(uint32_t& r0, uint32_t& r1, uint32_t a) {
    asm volatile("ldmatrix.sync.aligned.m8n8.x2.shared.b16 {%0,%1}, [%2];"
                 : "=r"(r0), "=r"(r1) : "r"(a));
}

#define CP16(dst, src) \
    asm volatile("cp.async.cg.shared.global [%0], [%1], 16;" :: "r"(dst), "l"(src))

// ---------------------------------------------------------------------------
// Kernel 1: masked_vec = (Q K^T) * SCALE * mask.  128x128 tile, BK=32,
// 3-stage cp.async pipeline, ldmatrix fragment loads, XOR-swizzled smem.
// ---------------------------------------------------------------------------
__global__ __launch_bounds__(256, 2) void qk_kernel(
    const float* __restrict__ Q, const float* __restrict__ K,
    const int* __restrict__ rep, float* __restrict__ attn_param)
{
    float* attn = attn_param ? attn_param : g_attn_scratch;
    const int bm = blockIdx.y, bn = blockIdx.x, b = blockIdx.z;
    const int m0 = bm * 128, n0 = bn * 128;
    const int tid = threadIdx.x;
    float* attn_b = attn + (size_t)b * S_ * S_;

    if (bn > bm) {
        float4 z = make_float4(0.f, 0.f, 0.f, 0.f);
        #pragma unroll
        for (int i = 0; i < 16; i++) {
            int idx = tid + i * 256;
            int r = idx >> 5, c = idx & 31;
            reinterpret_cast<float4*>(attn_b + (size_t)(m0 + r) * S_ + n0)[c] = z;
        }
        return;
    }

    extern __shared__ float smem[];
    const uint32_t smem_u = (uint32_t)__cvta_generic_to_shared(smem);

    const int warp = tid >> 5, lane = tid & 31;
    const int wm = warp & 1, wn = warp >> 1;
    const int gID = lane >> 2, tig = lane & 3;

    const float* Qb = Q + ((size_t)b * S_ + m0) * D_;
    const float* Kb = K + ((size_t)b * S_ + n0) * D_;

    // global->smem mapping (swizzled 16B granules, constant per thread)
    const int lr = tid >> 3, lc4 = tid & 7;
    const uint32_t sw_off = (uint32_t)(((lc4 ^ (lr & 7)) << 4));

    // ldmatrix lane address components
    const int a_ro = (lane & 7) + ((lane >> 4) << 3);  // row within 16-row block
    const int a_ck = (lane >> 3) & 1;                  // 16B chunk select
    const int l7 = lane & 7;

    float acc[4][4][4];
    #pragma unroll
    for (int i = 0; i < 4; i++)
        #pragma unroll
        for (int j = 0; j < 4; j++)
            #pragma unroll
            for (int r = 0; r < 4; r++) acc[i][j][r] = 0.f;

    #define QK_ISSUE(kk, st) do {                                              \
        uint32_t bA = smem_u + (uint32_t)(st) * 32768u;                        \
        uint32_t bB = bA + 16384u;                                             \
        _Pragma("unroll")                                                      \
        for (int i_ = 0; i_ < 4; i_++) {                                       \
            int r_ = lr + i_ * 32;                                             \
            uint32_t off_ = (uint32_t)(r_ * 128) + sw_off;                     \
            CP16(bA + off_, Qb + (size_t)r_ * D_ + (kk) + lc4 * 4);            \
            CP16(bB + off_, Kb + (size_t)r_ * D_ + (kk) + lc4 * 4);            \
        }                                                                      \
        asm volatile("cp.async.commit_group;");                                \
    } while (0)

    QK_ISSUE(0, 0);
    QK_ISSUE(32, 1);

    int s = 0;
    for (int t = 0; t < 16; t++) {
        if (t < 14) { asm volatile("cp.async.wait_group 1;"); }
        else        { asm volatile("cp.async.wait_group 0;"); }
        __syncthreads();
        if (t < 14) {
            int s2 = s + 2; if (s2 >= 3) s2 -= 3;
            QK_ISSUE((t + 2) * 32, s2);
        }
        uint32_t bA = smem_u + (uint32_t)s * 32768u;
        uint32_t bB = bA + 16384u;
        #pragma unroll
        for (int ks = 0; ks < 4; ks++) {
            float bf[4][2];
            #pragma unroll
            for (int in_ = 0; in_ < 4; in_++) {
                int n = wn * 32 + in_ * 8 + l7;
                uint32_t addr = bB + (uint32_t)(n * 128)
                              + (uint32_t)(((((ks << 1) + a_ck) ^ l7)) << 4);
                uint32_t r0, r1;
                ldsm2(r0, r1, addr);
                bf[in_][0] = u_tf32(r0);
                bf[in_][1] = u_tf32(r1);
            }
            #pragma unroll
            for (int im = 0; im < 4; im++) {
                int r = wm * 64 + im * 16 + a_ro;
                uint32_t addr = bA + (uint32_t)(r * 128)
                              + (uint32_t)(((((ks << 1) + a_ck) ^ l7)) << 4);
                uint32_t r0, r1, r2, r3;
                ldsm4(r0, r1, r2, r3, addr);
                float a[4] = { u_tf32(r0), u_tf32(r2), u_tf32(r1), u_tf32(r3) };
                #pragma unroll
                for (int in_ = 0; in_ < 4; in_++)
                    mma_tf32(acc[im][in_], a, bf[in_]);
            }
        }
        s = (s == 2) ? 0 : s + 1;
    }
    #undef QK_ISSUE

    // Epilogue: scale + mask, write masked_vec.
    const int* repb = rep + b * S_;
    #pragma unroll
    for (int im = 0; im < 4; im++) {
        int mA = m0 + wm * 64 + im * 16 + gID;
        int mB = mA + 8;
        int rqA = repb[mA], rqB = repb[mB];
        #pragma unroll
        for (int in_ = 0; in_ < 4; in_++) {
            int n = n0 + wn * 32 + in_ * 8 + tig * 2;
            int rk0 = repb[n], rk1 = repb[n + 1];
            float v00 = acc[im][in_][0] * SCALE;
            float v01 = acc[im][in_][1] * SCALE;
            float v10 = acc[im][in_][2] * SCALE;
            float v11 = acc[im][in_][3] * SCALE;
            attn_b[(size_t)mA * S_ + n]     = (n     < mA && rqA && rk0) ? v00 : 0.f;
            attn_b[(size_t)mA * S_ + n + 1] = (n + 1 < mA && rqA && rk1) ? v01 : 0.f;
            attn_b[(size_t)mB * S_ + n]     = (n     < mB && rqB && rk0) ? v10 : 0.f;
            attn_b[(size_t)mB * S_ + n + 1] = (n + 1 < mB && rqB && rk1) ? v11 : 0.f;
        }
    }
}

// ---------------------------------------------------------------------------
// Kernel 2: in-place row softmax, faithful to reference semantics.
// ---------------------------------------------------------------------------
__global__ __launch_bounds__(256) void softmax_kernel(
    float* attn_param, const int* __restrict__ rep)
{
    float* attn = attn_param ? attn_param : g_attn_scratch;
    const int q = blockIdx.x, b = blockIdx.y;
    float* row = attn + ((size_t)b * S_ + q) * S_;
    const int tid = threadIdx.x;

    float4 v = reinterpret_cast<float4*>(row)[tid];
    const int k0 = tid * 4;
    const int rq = rep[b * S_ + q];
    const int4 rk = reinterpret_cast<const int4*>(rep + b * S_)[tid];

    __shared__ float red_max[8];
    __shared__ float red_sum[8];

    float mx = fmaxf(fmaxf(v.x, v.y), fmaxf(v.z, v.w));
    #pragma unroll
    for (int o = 16; o; o >>= 1) mx = fmaxf(mx, __shfl_xor_sync(0xffffffffu, mx, o));
    if ((tid & 31) == 0) red_max[tid >> 5] = mx;
    __syncthreads();
    mx = red_max[0];
    #pragma unroll
    for (int w = 1; w < 8; w++) mx = fmaxf(mx, red_max[w]);

    const bool m0b = (k0     < q) && rq && rk.x;
    const bool m1b = (k0 + 1 < q) && rq && rk.y;
    const bool m2b = (k0 + 2 < q) && rq && rk.z;
    const bool m3b = (k0 + 3 < q) && rq && rk.w;
    float e0 = m0b ? __expf(v.x - mx) : 0.f;
    float e1 = m1b ? __expf(v.y - mx) : 0.f;
    float e2 = m2b ? __expf(v.z - mx) : 0.f;
    float e3 = m3b ? __expf(v.w - mx) : 0.f;

    float sden = (e0 + e1) + (e2 + e3);
    #pragma unroll
    for (int o = 16; o; o >>= 1) sden += __shfl_xor_sync(0xffffffffu, sden, o);
    if ((tid & 31) == 0) red_sum[tid >> 5] = sden;
    __syncthreads();
    sden = red_sum[0];
    #pragma unroll
    for (int w = 1; w < 8; w++) sden += red_sum[w];

    float s2 = sden + ((sden == 0.f) ? 1.f : 0.f);
    float inv = 1.f / (s2 + 1e-20f);

    v.x = e0 * inv; v.y = e1 * inv; v.z = e2 * inv; v.w = e3 * inv;
    reinterpret_cast<float4*>(row)[tid] = v;
}

// ---------------------------------------------------------------------------
// Kernel 3: out = attn_sm @ V.  Triangular K-loop, same pipeline structure.
// V stored [k][n] with stride 136 (bank = 8*tig + gID, conflict-free).
// ---------------------------------------------------------------------------
__global__ __launch_bounds__(256, 2) void pv_kernel(
    const float* attn_param, const float* __restrict__ V, float* __restrict__ out)
{
    const float* attn = attn_param ? attn_param : g_attn_scratch;
    const int bm = blockIdx.y, bn = blockIdx.x, b = blockIdx.z;
    const int m0 = bm * 128, n0 = bn * 128;
    const int tid = threadIdx.x;

    extern __shared__ float smem[];
    const uint32_t smem_u = (uint32_t)__cvta_generic_to_shared(smem);

    const int warp = tid >> 5, lane = tid & 31;
    const int wm = warp & 1, wn = warp >> 1;
    const int gID = lane >> 2, tig = lane & 3;

    const float* Ab = attn + ((size_t)b * S_ + m0) * S_;
    const float* Vb = V + (size_t)b * S_ * D_;

    const int lr = tid >> 3, lc4 = tid & 7;
    const uint32_t sw_off = (uint32_t)(((lc4 ^ (lr & 7)) << 4));
    const int vrow = tid >> 5, vcol = tid & 31;

    const int a_ro = (lane & 7) + ((lane >> 4) << 3);
    const int a_ck = (lane >> 3) & 1;
    const int l7 = lane & 7;

    float acc[4][4][4];
    #pragma unroll
    for (int i = 0; i < 4; i++)
        #pragma unroll
        for (int j = 0; j < 4; j++)
            #pragma unroll
            for (int r = 0; r < 4; r++) acc[i][j][r] = 0.f;

    const int NT = (bm + 1) * 4;  // k-tiles of 32, strictly-lower-tri bound

    #define PV_ISSUE(kk, st) do {                                              \
        uint32_t bA = smem_u + (uint32_t)(st) * 33792u;                        \
        uint32_t bB = bA + 16384u;                                             \
        _Pragma("unroll")                                                      \
        for (int i_ = 0; i_ < 4; i_++) {                                       \
            int r_ = lr + i_ * 32;                                             \
            CP16(bA + (uint32_t)(r_ * 128) + sw_off,                           \
                 Ab + (size_t)r_ * S_ + (kk) + lc4 * 4);                       \
            int rv_ = vrow + i_ * 8;                                           \
            CP16(bB + (uint32_t)((rv_ * 136 + vcol * 4) * 4),                  \
                 Vb + (size_t)((kk) + rv_) * D_ + n0 + vcol * 4);              \
        }                                                                      \
        asm volatile("cp.async.commit_group;");                                \
    } while (0)

    PV_ISSUE(0, 0);
    PV_ISSUE(32, 1);

    int s = 0;
    for (int t = 0; t < NT; t++) {
        if (t + 2 < NT) { asm volatile("cp.async.wait_group 1;"); }
        else            { asm volatile("cp.async.wait_group 0;"); }
        __syncthreads();
        if (t + 2 < NT) {
            int s2 = s + 2; if (s2 >= 3) s2 -= 3;
            PV_ISSUE((t + 2) * 32, s2);
        }
        uint32_t bA = smem_u + (uint32_t)s * 33792u;
        const float* Vs = smem + (size_t)s * 8448 + 4096;
        #pragma unroll
        for (int ks = 0; ks < 4; ks++) {
            float bf[4][2];
            #pragma unroll
            for (int in_ = 0; in_ < 4; in_++) {
                int nn = wn * 32 + in_ * 8 + gID;
                bf[in_][0] = to_tf32(Vs[(ks * 8 + tig) * 136 + nn]);
                bf[in_][1] = to_tf32(Vs[(ks * 8 + 4 + tig) * 136 + nn]);
            }
            #pragma unroll
            for (int im = 0; im < 4; im++) {
                int r = wm * 64 + im * 16 + a_ro;
                uint32_t addr = bA + (uint32_t)(r * 128)
                              + (uint32_t)(((((ks << 1) + a_ck) ^ l7)) << 4);
                uint32_t r0, r1, r2, r3;
                ldsm4(r0, r1, r2, r3, addr);
                float a[4] = { u_tf32(r0), u_tf32(r2), u_tf32(r1), u_tf32(r3) };
                #pragma unroll
                for (int in_ = 0; in_ < 4; in_++)
                    mma_tf32(acc[im][in_], a, bf[in_]);
            }
        }
        s = (s == 2) ? 0 : s + 1;
    }
    #undef PV_ISSUE

    #pragma unroll
    for (int im = 0; im < 4; im++) {
        int mA = m0 + wm * 64 + im * 16 + gID;
        int mB = mA + 8;
        #pragma unroll
        for (int in_ = 0; in_ < 4; in_++) {
            int n = n0 + wn * 32 + in_ * 8 + tig * 2;
            out[((size_t)b * S_ + mA) * D_ + n]     = acc[im][in_][0];
            out[((size_t)b * S_ + mA) * D_ + n + 1] = acc[im][in_][1];
            out[((size_t)b * S_ + mB) * D_ + n]     = acc[im][in_][2];
            out[((size_t)b * S_ + mB) * D_ + n + 1] = acc[im][in_][3];
        }
    }
}

extern "C" void kernel_launch(void* const* d_in, const int* in_sizes, int n_in,
                              void* d_out, int out_size)
{
    const float* q   = (const float*)d_in[0];
    const float* k   = (const float*)d_in[1];
    const float* v   = (const float*)d_in[2];
    const int*   rep = (const int*)d_in[3];
    float* out = (float*)d_out;

    const long OUT_ELEMS  = (long)B_ * S_ * D_;   // 16,777,216
    const long ATTN_ELEMS = (long)B_ * S_ * S_;   // 33,554,432

    float* attn = nullptr;  // nullptr -> kernels fall back to g_attn_scratch
    if ((long)out_size >= OUT_ELEMS + ATTN_ELEMS)
        attn = out + OUT_ELEMS;

    const int QK_SMEM = 3 * 32768;   // 98304 B
    const int PV_SMEM = 3 * 33792;   // 101376 B
    cudaFuncSetAttribute(qk_kernel, cudaFuncAttributeMaxDynamicSharedMemorySize, QK_SMEM);
    cudaFuncSetAttribute(pv_kernel, cudaFuncAttributeMaxDynamicSharedMemorySize, PV_SMEM);

    dim3 g1(8, 8, B_);
    qk_kernel<<<g1, 256, QK_SMEM>>>(q, k, rep, attn);

    dim3 g2(S_, B_);
    softmax_kernel<<<g2, 256>>>(attn, rep);

    dim3 g3(4, 8, B_);
    pv_kernel<<<g3, 256, PV_SMEM>>>(attn, v, out);
}